// round 1
// baseline (speedup 1.0000x reference)
#include <cuda_runtime.h>
#include <cuda_bf16.h>

// Prefix offsets of batch_num_nodes (device-global scratch; no allocations).
__device__ int g_node_off[1025];

__global__ void spp_prefix_kernel(const int* __restrict__ bn, int B) {
    if (blockIdx.x == 0 && threadIdx.x == 0) {
        int acc = 0;
        g_node_off[0] = 0;
        for (int i = 0; i < B; ++i) {
            acc += bn[i];
            g_node_off[i + 1] = acc;
        }
    }
}

// One warp per node: 32 lanes x float4 = 128 floats.
// Scaled row is reduced into the (graph, row, col) segment with red.global.add.v4.f32
// (REDG.128, no return) -- output is 2MB and L2-resident.
__global__ void __launch_bounds__(256) spp_pool_kernel(
    const float* __restrict__ feat,
    const int*   __restrict__ xy,
    float*       __restrict__ out,
    int N, int D, int G, int B)
{
    extern __shared__ int s_off[];
    for (int i = threadIdx.x; i <= B; i += blockDim.x) s_off[i] = g_node_off[i];
    __syncthreads();

    const int lane   = threadIdx.x & 31;
    const int warp   = (blockIdx.x * blockDim.x + threadIdx.x) >> 5;
    const int nwarps = (gridDim.x * blockDim.x) >> 5;

    for (int node = warp; node < N; node += nwarps) {
        // xy row (uniform across warp -> broadcast loads)
        const int r  = __ldg(&xy[3 * node + 0]);
        const int c  = __ldg(&xy[3 * node + 1]);
        const int dv = __ldg(&xy[3 * node + 2]);

        // graph id: binary search in prefix offsets (B<=1024, 6-10 LDS)
        int lo = 0, hi = B;
        while (hi - lo > 1) {
            int mid = (lo + hi) >> 1;
            if (s_off[mid] <= node) lo = mid; else hi = mid;
        }
        const int seg = (lo * G + r) * G + c;
        const float inv = 1.0f / (float)dv;

        const float4* frow = reinterpret_cast<const float4*>(feat + (size_t)node * D);
        float*        orow = out + (size_t)seg * D;

        #pragma unroll 1
        for (int d4 = lane; d4 * 4 < D; d4 += 32) {
            float4 v = __ldg(&frow[d4]);
            v.x *= inv; v.y *= inv; v.z *= inv; v.w *= inv;
            // vector reduction (sm_90+): 16B-aligned (seg*D is 512B-aligned, d4*16)
            asm volatile(
                "red.global.add.v4.f32 [%0], {%1, %2, %3, %4};"
                :: "l"(orow + d4 * 4), "f"(v.x), "f"(v.y), "f"(v.z), "f"(v.w)
                : "memory");
        }
    }
}

extern "C" void kernel_launch(void* const* d_in, const int* in_sizes, int n_in,
                              void* d_out, int out_size) {
    const float* feat = (const float*)d_in[0];
    const int*   xy   = (const int*)d_in[1];
    const int*   bn   = (const int*)d_in[2];
    float*       out  = (float*)d_out;

    const int B = in_sizes[2];          // 64
    const int N = in_sizes[1] / 3;      // 2,000,000
    const int D = in_sizes[0] / N;      // 128
    // out_size = B * G * G * D
    int gg = out_size / (B * D);        // G*G = 64
    int G = 1;
    while (G * G < gg) ++G;             // G = 8

    // Output accumulates via atomics -> must be zeroed every replay.
    cudaMemsetAsync(d_out, 0, (size_t)out_size * sizeof(float), 0);

    spp_prefix_kernel<<<1, 32>>>(bn, B);

    const int threads = 256;
    const int warps_per_block = threads / 32;
    int blocks = (N + warps_per_block - 1) / warps_per_block;
    if (blocks > 8192) blocks = 8192;   // grid-stride; ~30 nodes/warp
    size_t smem = (size_t)(B + 1) * sizeof(int);
    spp_pool_kernel<<<blocks, threads, smem>>>(feat, xy, out, N, D, G, B);
}

// round 2
// speedup vs baseline: 1.1685x; 1.1685x over previous
#include <cuda_runtime.h>
#include <cuda_bf16.h>

// Prefix offsets of batch_num_nodes (device-global scratch; no allocations).
__device__ int g_node_off[1025];

__global__ void spp_prefix_kernel(const int* __restrict__ bn, int B) {
    if (blockIdx.x == 0 && threadIdx.x == 0) {
        int acc = 0;
        g_node_off[0] = 0;
        for (int i = 0; i < B; ++i) {
            acc += bn[i];
            g_node_off[i + 1] = acc;
        }
    }
}

// Warp-batched scatter-add:
//   prologue: each lane computes seg/inv for ONE node (32 nodes per batch),
//   main loop: broadcast (seg, inv) per node, 32 lanes move the 512B row with
//   one LDG.128 + red.global.add.v4.f32 each.
__global__ void __launch_bounds__(256) spp_pool_kernel(
    const float* __restrict__ feat,
    const int*   __restrict__ xy,
    float*       __restrict__ out,
    int N, int D, int G, int B)
{
    extern __shared__ int s_off[];
    for (int i = threadIdx.x; i <= B; i += blockDim.x) s_off[i] = g_node_off[i];
    __syncthreads();

    const int lane    = threadIdx.x & 31;
    const int warp    = (blockIdx.x * blockDim.x + threadIdx.x) >> 5;
    const int nwarps  = (gridDim.x * blockDim.x) >> 5;

    // grid-stride over 32-node batches
    for (long long base = (long long)warp * 32; base < N;
         base += (long long)nwarps * 32) {

        // ---- prologue: per-lane node metadata ----
        long long mynode = base + lane;
        int nd = (mynode < N) ? (int)mynode : (N - 1);

        const int r  = __ldg(&xy[3 * nd + 0]);
        const int c  = __ldg(&xy[3 * nd + 1]);
        const int dv = __ldg(&xy[3 * nd + 2]);

        // graph id: binary search in prefix offsets (per-lane, warp-parallel)
        int lo = 0, hi = B;
        while (hi - lo > 1) {
            int mid = (lo + hi) >> 1;
            if (s_off[mid] <= nd) lo = mid; else hi = mid;
        }
        const int   myseg = (lo * G + r) * G + c;
        const float myinv = 1.0f / (float)dv;

        const int cnt = (N - base >= 32) ? 32 : (int)(N - base);
        const float4* frow =
            reinterpret_cast<const float4*>(feat + (size_t)base * D) + lane;

        // ---- main loop: one node per iteration, whole warp cooperates ----
        #pragma unroll 4
        for (int j = 0; j < cnt; ++j) {
            const int   seg = __shfl_sync(0xffffffffu, myseg, j);
            const float inv = __shfl_sync(0xffffffffu, myinv, j);

            float4 v = __ldg(frow + (size_t)j * (D / 4));
            v.x *= inv; v.y *= inv; v.z *= inv; v.w *= inv;

            float* dst = out + (size_t)seg * D + lane * 4;
            asm volatile(
                "red.global.add.v4.f32 [%0], {%1, %2, %3, %4};"
                :: "l"(dst), "f"(v.x), "f"(v.y), "f"(v.z), "f"(v.w)
                : "memory");
        }
    }
}

extern "C" void kernel_launch(void* const* d_in, const int* in_sizes, int n_in,
                              void* d_out, int out_size) {
    const float* feat = (const float*)d_in[0];
    const int*   xy   = (const int*)d_in[1];
    const int*   bn   = (const int*)d_in[2];
    float*       out  = (float*)d_out;

    const int B = in_sizes[2];          // 64
    const int N = in_sizes[1] / 3;      // 2,000,000
    const int D = in_sizes[0] / N;      // 128
    int gg = out_size / (B * D);        // G*G
    int G = 1;
    while (G * G < gg) ++G;             // G = 8

    // Output accumulates via atomics -> must be zeroed every replay.
    cudaMemsetAsync(d_out, 0, (size_t)out_size * sizeof(float), 0);

    spp_prefix_kernel<<<1, 32>>>(bn, B);

    const int threads = 256;
    const int warps_per_block = threads / 32;        // 8
    // one 32-node batch per warp (single pass), grid-stride as safety net
    long long batches = ((long long)N + 31) / 32;
    int blocks = (int)((batches + warps_per_block - 1) / warps_per_block);
    if (blocks > 65535) blocks = 65535;
    size_t smem = (size_t)(B + 1) * sizeof(int);
    spp_pool_kernel<<<blocks, threads, smem>>>(feat, xy, out, N, D, G, B);
}